// round 5
// baseline (speedup 1.0000x reference)
#include <cuda_runtime.h>

// LengthRegulator: B=32, T=1024, C=384, M(max_mel_len)=4096  (fixed by setup_inputs)
// out[b,f,:] = x[b, upper_bound(cumsum(dur[b]), f), :] if f < total[b] else 0
// plus total[b] appended to the output buffer AS FLOAT32 (harness packs the
// whole tuple in the __output__ dtype; confirmed: raw int bits -> rel_err 1.0).
// Durations are int32 (JAX x64 disabled; confirmed: output 0 exact with int path).

#define BB 32
#define TT 1024
#define CC 384
#define MM 4096
#define C4 (CC / 4)          // 96 float4 per row
#define MAIN_ELEMS ((long long)BB * MM * CC)   // 50,331,648

__device__ int g_cs[BB][TT];       // int cumsum (values <= 7168)
__device__ int g_tok[BB * MM];     // token index per frame, -1 => zero-fill

// ---------------------------------------------------------------------------
// Stage 1: per-batch inclusive scan of durations (Hillis-Steele in smem).
// Writes total[b] into the output tail as float32.
// ---------------------------------------------------------------------------
__global__ void lr_scan_kernel(const int* __restrict__ dur,
                               float* __restrict__ out_base) {
    __shared__ int s[TT];
    const int b = blockIdx.x;
    const int t = threadIdx.x;
    s[t] = dur[b * TT + t];
    __syncthreads();
    #pragma unroll
    for (int off = 1; off < TT; off <<= 1) {
        int add = (t >= off) ? s[t - off] : 0;
        __syncthreads();
        s[t] += add;
        __syncthreads();
    }
    g_cs[b][t] = s[t];
    if (t == TT - 1) {
        out_base[MAIN_ELEMS + b] = (float)s[t];   // total as float32 value
    }
}

// ---------------------------------------------------------------------------
// Stage 2: frame -> token map. Exact upper_bound via bit construction:
// pos = largest p such that cs[p-1] <= f  (== searchsorted side='right').
// ---------------------------------------------------------------------------
__global__ void lr_tokmap_kernel() {
    __shared__ int cs[TT];
    const int b = blockIdx.y;
    for (int i = threadIdx.x; i < TT; i += blockDim.x)
        cs[i] = g_cs[b][i];
    __syncthreads();

    const int f = blockIdx.x * blockDim.x + threadIdx.x;
    const int total = cs[TT - 1];

    int pos = 0;
    #pragma unroll
    for (int step = TT / 2; step > 0; step >>= 1) {
        int cand = pos + step;               // cand-1 <= 1022
        if (cs[cand - 1] <= f) pos = cand;
    }
    // pos == upper_bound for answers 0..1023; frames needing 1024 are invalid.
    g_tok[b * MM + f] = (f < total) ? pos : -1;
}

// ---------------------------------------------------------------------------
// Stage 3: row gather, float4 vectorized, one thread per float4.
// Streaming stores (__stcs) keep x's read lines resident in L2.
// ---------------------------------------------------------------------------
__global__ void lr_gather_kernel(const float4* __restrict__ x4,
                                 float4* __restrict__ out4) {
    const int idx = blockIdx.x * blockDim.x + threadIdx.x;   // < 12,582,912
    const int row = idx / C4;          // b * MM + f
    const int c   = idx - row * C4;
    const int b   = row >> 12;         // row / MM
    const int tok = g_tok[row];
    float4 v = make_float4(0.f, 0.f, 0.f, 0.f);
    if (tok >= 0)
        v = __ldg(&x4[(b * TT + tok) * C4 + c]);
    __stcs(&out4[idx], v);
}

// ---------------------------------------------------------------------------

extern "C" void kernel_launch(void* const* d_in, const int* in_sizes, int n_in,
                              void* d_out, int out_size) {
    const float4* x4 = (const float4*)d_in[0];
    const int* dur = (const int*)d_in[1];
    float* out = (float*)d_out;

    lr_scan_kernel<<<BB, TT>>>(dur, out);

    dim3 g2(MM / 256, BB);
    lr_tokmap_kernel<<<g2, 256>>>();

    const int n4 = (int)(MAIN_ELEMS / 4);          // 12,582,912
    lr_gather_kernel<<<n4 / 256, 256>>>(x4, (float4*)d_out);
}

// round 6
// speedup vs baseline: 1.1920x; 1.1920x over previous
#include <cuda_runtime.h>

// LengthRegulator: B=32, T=1024, C=384, M=4096. Durations int32; totals appended
// to out as float32 values (both confirmed by R4/R5 bench).

#define BB 32
#define TT 1024
#define CC 384
#define MM 4096
#define C4 (CC / 4)                              // 96 float4 per row
#define MAIN_ELEMS ((long long)BB * MM * CC)     // 50,331,648
#define N4 (BB * MM * C4)                        // 12,582,912 float4
#define HALF (N4 / 2)                            // 6,291,456

__device__ int g_tok[BB * MM];     // token index per frame, -1 => zero-fill

// ---------------------------------------------------------------------------
// Fused stage 1+2: warp-shfl scan of durations + frame->token map.
// 32 blocks x 1024 threads. 2 barriers for the scan instead of 20.
// ---------------------------------------------------------------------------
__global__ void lr_prep_kernel(const int* __restrict__ dur,
                               float* __restrict__ out_base) {
    __shared__ int cs[TT];
    __shared__ int wsum[32];
    const int b = blockIdx.x;
    const int t = threadIdx.x;
    const int lane = t & 31;
    const int wid = t >> 5;

    int v = dur[b * TT + t];
    // inclusive warp scan
    #pragma unroll
    for (int off = 1; off < 32; off <<= 1) {
        int n = __shfl_up_sync(0xffffffffu, v, off);
        if (lane >= off) v += n;
    }
    if (lane == 31) wsum[wid] = v;
    __syncthreads();
    if (wid == 0) {
        int s = wsum[lane];
        #pragma unroll
        for (int off = 1; off < 32; off <<= 1) {
            int n = __shfl_up_sync(0xffffffffu, s, off);
            if (lane >= off) s += n;
        }
        wsum[lane] = s;
    }
    __syncthreads();
    int base = (wid > 0) ? wsum[wid - 1] : 0;
    cs[t] = v + base;
    __syncthreads();

    const int total = cs[TT - 1];
    if (t == TT - 1)
        out_base[MAIN_ELEMS + b] = (float)total;   // total as float32 value

    // 4 frames per thread, strided for coalesced g_tok stores.
    #pragma unroll
    for (int k = 0; k < MM / TT; ++k) {
        const int f = t + k * TT;
        // upper_bound via bit construction: largest pos with cs[pos-1] <= f
        int pos = 0;
        #pragma unroll
        for (int step = TT / 2; step > 0; step >>= 1) {
            int cand = pos + step;               // cand-1 <= 1022
            if (cs[cand - 1] <= f) pos = cand;
        }
        g_tok[b * MM + f] = (f < total) ? pos : -1;
    }
}

// ---------------------------------------------------------------------------
// Stage 3: row gather, 2 independent float4 streams per thread (MLP=2).
// Both streams perfectly coalesced; __stcs keeps x's lines resident in L2.
// ---------------------------------------------------------------------------
__global__ void lr_gather_kernel(const float4* __restrict__ x4,
                                 float4* __restrict__ out4) {
    const int i = blockIdx.x * blockDim.x + threadIdx.x;     // < HALF
    const int idx0 = i;
    const int idx1 = i + HALF;

    const int row0 = idx0 / C4;
    const int c0   = idx0 - row0 * C4;
    const int b0   = row0 >> 12;
    const int row1 = idx1 / C4;
    const int c1   = idx1 - row1 * C4;
    const int b1   = row1 >> 12;

    const int t0 = g_tok[row0];
    const int t1 = g_tok[row1];

    float4 v0 = make_float4(0.f, 0.f, 0.f, 0.f);
    float4 v1 = make_float4(0.f, 0.f, 0.f, 0.f);
    if (t0 >= 0) v0 = __ldg(&x4[(b0 * TT + t0) * C4 + c0]);
    if (t1 >= 0) v1 = __ldg(&x4[(b1 * TT + t1) * C4 + c1]);

    __stcs(&out4[idx0], v0);
    __stcs(&out4[idx1], v1);
}

// ---------------------------------------------------------------------------

extern "C" void kernel_launch(void* const* d_in, const int* in_sizes, int n_in,
                              void* d_out, int out_size) {
    const float4* x4 = (const float4*)d_in[0];
    const int* dur = (const int*)d_in[1];
    float* out = (float*)d_out;

    lr_prep_kernel<<<BB, TT>>>(dur, out);
    lr_gather_kernel<<<HALF / 256, 256>>>(x4, (float4*)d_out);
}

// round 7
// speedup vs baseline: 1.3209x; 1.1082x over previous
#include <cuda_runtime.h>

// LengthRegulator: B=32, T=1024, C=384, M=4096. Durations int32; totals appended
// to out as float32 values (confirmed R4/R5).

#define BB 32
#define TT 1024
#define CC 384
#define MM 4096
#define C4 (CC / 4)                              // 96 float4 per row
#define MAIN_ELEMS ((long long)BB * MM * CC)     // 50,331,648
#define N4 (BB * MM * C4)                        // 12,582,912 float4
#define QTR (N4 / 4)                             // 3,145,728

__device__ int g_tok[BB * MM];     // token index per frame, -1 => zero-fill

// ---------------------------------------------------------------------------
// Fused scan + tokmap. grid = (4, BB): 4 blocks per batch, each redundantly
// computes the (cheap) shfl scan, then resolves 1024 frames (1 per thread).
// ---------------------------------------------------------------------------
__global__ void lr_prep_kernel(const int* __restrict__ dur,
                               float* __restrict__ out_base) {
    __shared__ int cs[TT];
    __shared__ int wsum[32];
    const int b = blockIdx.y;
    const int t = threadIdx.x;
    const int lane = t & 31;
    const int wid = t >> 5;

    int v = dur[b * TT + t];
    #pragma unroll
    for (int off = 1; off < 32; off <<= 1) {
        int n = __shfl_up_sync(0xffffffffu, v, off);
        if (lane >= off) v += n;
    }
    if (lane == 31) wsum[wid] = v;
    __syncthreads();
    if (wid == 0) {
        int s = wsum[lane];
        #pragma unroll
        for (int off = 1; off < 32; off <<= 1) {
            int n = __shfl_up_sync(0xffffffffu, s, off);
            if (lane >= off) s += n;
        }
        wsum[lane] = s;
    }
    __syncthreads();
    int base = (wid > 0) ? wsum[wid - 1] : 0;
    cs[t] = v + base;
    __syncthreads();

    const int total = cs[TT - 1];
    if (blockIdx.x == 0 && t == TT - 1)
        out_base[MAIN_ELEMS + b] = (float)total;   // total as float32 value

    const int f = blockIdx.x * TT + t;             // one frame per thread
    // upper_bound via bit construction: largest pos with cs[pos-1] <= f
    int pos = 0;
    #pragma unroll
    for (int step = TT / 2; step > 0; step >>= 1) {
        int cand = pos + step;                     // cand-1 <= 1022
        if (cs[cand - 1] <= f) pos = cand;
    }
    g_tok[b * MM + f] = (f < total) ? pos : -1;
}

// ---------------------------------------------------------------------------
// Gather: 4 independent coalesced float4 streams per thread (MLP=4).
// __stcs streaming stores keep x's read lines resident in L2.
// ---------------------------------------------------------------------------
__global__ void lr_gather_kernel(const float4* __restrict__ x4,
                                 float4* __restrict__ out4) {
    const int i = blockIdx.x * blockDim.x + threadIdx.x;     // < QTR

    int idx[4], tok[4], src[4];
    #pragma unroll
    for (int k = 0; k < 4; ++k) {
        idx[k] = i + k * QTR;
        const int row = idx[k] / C4;               // b * MM + f
        const int c   = idx[k] - row * C4;
        const int b   = row >> 12;
        tok[k] = g_tok[row];
        src[k] = (b * TT + tok[k]) * C4 + c;
    }

    float4 val[4];
    #pragma unroll
    for (int k = 0; k < 4; ++k) {
        val[k] = make_float4(0.f, 0.f, 0.f, 0.f);
        if (tok[k] >= 0) val[k] = __ldg(&x4[src[k]]);
    }

    #pragma unroll
    for (int k = 0; k < 4; ++k)
        __stcs(&out4[idx[k]], val[k]);
}

// ---------------------------------------------------------------------------

extern "C" void kernel_launch(void* const* d_in, const int* in_sizes, int n_in,
                              void* d_out, int out_size) {
    const float4* x4 = (const float4*)d_in[0];
    const int* dur = (const int*)d_in[1];
    float* out = (float*)d_out;

    dim3 gprep(MM / TT, BB);                       // (4, 32)
    lr_prep_kernel<<<gprep, TT>>>(dur, out);
    lr_gather_kernel<<<QTR / 256, 256>>>(x4, (float4*)d_out);
}